// round 7
// baseline (speedup 1.0000x reference)
#include <cuda_runtime.h>

typedef unsigned long long u64;
typedef unsigned int u32;

#define NFRAME 300
#define LFRAME 512
#define NLAG   256
#define TSAMP  20000
#define BFDIM  200          // 4 * 50

// ---- shared memory layout (BYTE offsets) ----
// SW  region: 2 channels x 784 floats (windowed frame, circularly extended), swizzled
// SWS region: shift-by-one copy, 2 x 784 floats, swizzled (32B pad keeps it 16B-chunk aligned)
// ACF region: 2 x 256 floats, 128B-aligned, NOT swizzled (epilogue staging)
#define SW_B    0
#define CH_B    3136                 // 784 * 4 : channel stride in bytes
#define SWS_B   6304                 // (2*784 + 8) * 4
#define ACF_B   12672                // 128B-aligned, > SWS end (12576): no row sharing
#define SHM_FLOATS ((ACF_B + 2*NLAG*4) / 4)

// SW128-style software swizzle: permutes 16B chunks within each 128B row.
// Kills the 64B-stride bank conflicts of the b-window loads (verified: lanes
// spread exactly 4 per 4-bank group -> 4-cycle LDS.128 floor).
#define SWZ(b) ((b) ^ (((b) >> 3) & 0x70))
#define LD16(off)      (*(const ulonglong2*)(sc + SWZ((u32)(off))))
#define STSW(off, val) (*(float*)(scw + SWZ((u32)(off))) = (val))

// Packed fp32x2 FMA (Blackwell FFMA2 — only reachable via PTX fma.rn.f32x2)
#define FMA2(acc, a, b) asm("fma.rn.f32x2 %0, %1, %2, %0;" : "+l"(acc) : "l"(a), "l"(b))

// One macro-step: 8 consecutive n values x 8 lags (stride 2) = 64 packed MACs.
// Invariant on entry: V0..V11 hold sb[NN+0 .. NN+23] as (lo,hi) fp32 pairs.
// Loads refill V12..V15 with sb[NN+24 .. NN+31] for the next (rotated) step.
#define STEP(NN, V0,V1,V2,V3,V4,V5,V6,V7,V8,V9,V10,V11,V12,V13,V14,V15)               \
  {                                                                                    \
    ulonglong2 ta0 = LD16(aoff + 4*(NN));                                              \
    ulonglong2 ta1 = LD16(aoff + 4*(NN) + 16);                                         \
    ulonglong2 tb0 = LD16(boff + 4*(NN) + 96);                                         \
    ulonglong2 tb1 = LD16(boff + 4*(NN) + 112);                                        \
    u64 a0 = ta0.x, a1 = ta0.y, a2 = ta1.x, a3 = ta1.y;                                \
    FMA2(acc0, a0, V0);  FMA2(acc1, a0, V1);  FMA2(acc2, a0, V2);  FMA2(acc3, a0, V3); \
    FMA2(acc4, a0, V4);  FMA2(acc5, a0, V5);  FMA2(acc6, a0, V6);  FMA2(acc7, a0, V7); \
    FMA2(acc0, a1, V1);  FMA2(acc1, a1, V2);  FMA2(acc2, a1, V3);  FMA2(acc3, a1, V4); \
    FMA2(acc4, a1, V5);  FMA2(acc5, a1, V6);  FMA2(acc6, a1, V7);  FMA2(acc7, a1, V8); \
    FMA2(acc0, a2, V2);  FMA2(acc1, a2, V3);  FMA2(acc2, a2, V4);  FMA2(acc3, a2, V5); \
    FMA2(acc4, a2, V6);  FMA2(acc5, a2, V7);  FMA2(acc6, a2, V8);  FMA2(acc7, a2, V9); \
    FMA2(acc0, a3, V3);  FMA2(acc1, a3, V4);  FMA2(acc2, a3, V5);  FMA2(acc3, a3, V6); \
    FMA2(acc4, a3, V7);  FMA2(acc5, a3, V8);  FMA2(acc6, a3, V9);  FMA2(acc7, a3, V10);\
    V12 = tb0.x; V13 = tb0.y; V14 = tb1.x; V15 = tb1.y;                                \
  }

__global__ void __launch_bounds__(64)
acf_kernel(const float* __restrict__ in, float* __restrict__ out)
{
    __shared__ __align__(128) float shm[SHM_FLOATS];
    const char* sc  = (const char*)shm;
    char*       scw = (char*)shm;

    const int t   = blockIdx.x;   // frame index 0..299
    const int bf  = blockIdx.y;   // fused (batch, freq) 0..199
    const int tid = threadIdx.x;  // 0..63

    // Exact replica of np.linspace(0, 19488, 300).astype(int64)
    const double delta = (double)(TSAMP - LFRAME) / (double)(NFRAME - 1);
    const int S = (t == NFRAME - 1) ? (TSAMP - LFRAME) : (int)((double)t * delta);

    // -------- load + window + build circular (and shift-by-1) extensions --------
    // input layout: nervegram[b, f, time, c] -> channels adjacent => one float2 per time
    const float2* __restrict__ src = (const float2*)in + (size_t)bf * TSAMP + S;
    #pragma unroll
    for (int it = 0; it < 8; ++it) {
        const int n = tid + 64 * it;                       // 0..511
        const float2 v = src[n];
        const float wn = 0.5f - 0.5f * __cosf((float)n * 0.012271846303085130f); // 2*pi/512
        const float f0 = wn * v.x;
        const float f1 = wn * v.y;
        STSW(4*n,            f0);
        STSW(4*n + CH_B,     f1);
        const int m = (n + 511) & 511;                     // n-1 mod 512
        STSW(SWS_B + 4*m,        f0);
        STSW(SWS_B + 4*m + CH_B, f1);
        if (n < 272) {
            STSW(4*(n + 512),        f0);
            STSW(4*(n + 512) + CH_B, f1);
        }
        if (n >= 1 && n < 273) {
            STSW(SWS_B + 4*(n + 511),        f0);
            STSW(SWS_B + 4*(n + 511) + CH_B, f1);
        }
    }
    __syncthreads();

    // -------- per-thread lag assignment --------
    // warp = channel; lane -> (parity p, group g); lags = 16g + p + {0,2,...,14}
    const int c    = tid >> 5;
    const int lane = tid & 31;
    const int p    = lane & 1;
    const int g    = lane >> 1;
    const int K    = 16 * g + p;

    const u32 aoff = (u32)(CH_B * c);                                 // f_c[n]
    const u32 boff = aoff + 64u * g + (p ? (u32)SWS_B : 0u);          // f_c[(n + K + .) mod 512]

    u64 acc0 = 0, acc1 = 0, acc2 = 0, acc3 = 0, acc4 = 0, acc5 = 0, acc6 = 0, acc7 = 0;
    u64 U0,U1,U2,U3,U4,U5,U6,U7,U8,U9,U10,U11,U12,U13,U14,U15;

    // prologue: U0..U11 = sb[0..23]
    {
        ulonglong2 q;
        q = LD16(boff +  0); U0  = q.x; U1  = q.y;
        q = LD16(boff + 16); U2  = q.x; U3  = q.y;
        q = LD16(boff + 32); U4  = q.x; U5  = q.y;
        q = LD16(boff + 48); U6  = q.x; U7  = q.y;
        q = LD16(boff + 64); U8  = q.x; U9  = q.y;
        q = LD16(boff + 80); U10 = q.x; U11 = q.y;
    }

    // main loop: 64 macro-steps of 8 n-values, window registers rotate with period 4
    for (int n8 = 0; n8 < 512; n8 += 32) {
        STEP(n8,      U0,U1,U2,U3,U4,U5,U6,U7,U8,U9,U10,U11,U12,U13,U14,U15);
        STEP(n8 +  8, U4,U5,U6,U7,U8,U9,U10,U11,U12,U13,U14,U15,U0,U1,U2,U3);
        STEP(n8 + 16, U8,U9,U10,U11,U12,U13,U14,U15,U0,U1,U2,U3,U4,U5,U6,U7);
        STEP(n8 + 24, U12,U13,U14,U15,U0,U1,U2,U3,U4,U5,U6,U7,U8,U9,U10,U11);
    }

    // -------- epilogue: fold packed halves, relu, stage per-channel ACF --------
    float* sacf = shm + (ACF_B / 4);
    {
        float lo, hi;
        asm("mov.b64 {%0,%1}, %2;" : "=f"(lo), "=f"(hi) : "l"(acc0));
        sacf[c * NLAG + K +  0] = fmaxf(lo + hi, 0.f);
        asm("mov.b64 {%0,%1}, %2;" : "=f"(lo), "=f"(hi) : "l"(acc1));
        sacf[c * NLAG + K +  2] = fmaxf(lo + hi, 0.f);
        asm("mov.b64 {%0,%1}, %2;" : "=f"(lo), "=f"(hi) : "l"(acc2));
        sacf[c * NLAG + K +  4] = fmaxf(lo + hi, 0.f);
        asm("mov.b64 {%0,%1}, %2;" : "=f"(lo), "=f"(hi) : "l"(acc3));
        sacf[c * NLAG + K +  6] = fmaxf(lo + hi, 0.f);
        asm("mov.b64 {%0,%1}, %2;" : "=f"(lo), "=f"(hi) : "l"(acc4));
        sacf[c * NLAG + K +  8] = fmaxf(lo + hi, 0.f);
        asm("mov.b64 {%0,%1}, %2;" : "=f"(lo), "=f"(hi) : "l"(acc5));
        sacf[c * NLAG + K + 10] = fmaxf(lo + hi, 0.f);
        asm("mov.b64 {%0,%1}, %2;" : "=f"(lo), "=f"(hi) : "l"(acc6));
        sacf[c * NLAG + K + 12] = fmaxf(lo + hi, 0.f);
        asm("mov.b64 {%0,%1}, %2;" : "=f"(lo), "=f"(hi) : "l"(acc7));
        sacf[c * NLAG + K + 14] = fmaxf(lo + hi, 0.f);
    }
    __syncthreads();

    // -------- normalize per channel, mean over channels, store --------
    const float n0 = sacf[0];
    const float n1 = sacf[NLAG];
    const float i0 = (n0 == 0.f) ? 1.f : rsqrtf(n0);
    const float i1 = (n1 == 0.f) ? 1.f : rsqrtf(n1);
    float* __restrict__ op = out + ((size_t)bf * NFRAME + t) * NLAG;
    #pragma unroll
    for (int k = tid; k < NLAG; k += 64) {
        op[k] = 0.5f * (sacf[k] * i0 + sacf[NLAG + k] * i1);
    }
}

extern "C" void kernel_launch(void* const* d_in, const int* in_sizes, int n_in,
                              void* d_out, int out_size)
{
    (void)in_sizes; (void)n_in; (void)out_size;
    const float* in = (const float*)d_in[0];
    float* out = (float*)d_out;
    dim3 grid(NFRAME, BFDIM);
    acf_kernel<<<grid, 64>>>(in, out);
}

// round 8
// speedup vs baseline: 1.9460x; 1.9460x over previous
#include <cuda_runtime.h>

typedef unsigned long long u64;

#define NFRAME 300
#define LFRAME 512
#define NLAG   256
#define TSAMP  20000
#define BFDIM  200          // 4 * 50

// ---- shared memory layout (in float words) ----
// EXT = 808: circular extension covers max read index 803 (g=15: 240 + r=28 + 535)
// sw[c][808]   : windowed frame, circularly extended: sw[c][m] = f_c[m % 512]
// sws[c][808]  : shift-by-one copy: sws[c][m] = f_c[(m+1) % 512]
// sacf[2][256] : per-channel relu'd ACF for the normalization / channel-mean epilogue
#define EXT    808
#define SW0    0
#define SWS0   (2*EXT + 8)
#define ACF0   (SWS0 + 2*EXT)
#define SHMW   (ACF0 + 2*256)

// Packed fp32x2 FMA (Blackwell FFMA2 — only reachable via PTX fma.rn.f32x2)
#define FMA2(acc, a, b) asm("fma.rn.f32x2 %0, %1, %2, %0;" : "+l"(acc) : "l"(a), "l"(b))

// One macro-step: 8 consecutive n values x 8 lags (stride 2) = 64 packed MACs.
// Invariant on entry: V0..V11 hold sb[NN+0 .. NN+23] as (lo,hi) fp32 pairs.
// Loads refill V12..V15 with sb[NN+24 .. NN+31] for the next (rotated) step.
// Pure ptr+immediate addressing — no per-load arithmetic.
#define STEP(NN, V0,V1,V2,V3,V4,V5,V6,V7,V8,V9,V10,V11,V12,V13,V14,V15)               \
  {                                                                                    \
    ulonglong2 ta0 = *(const ulonglong2 *)(sa + (NN));                                 \
    ulonglong2 ta1 = *(const ulonglong2 *)(sa + (NN) + 4);                             \
    ulonglong2 tb0 = *(const ulonglong2 *)(sb + (NN) + 24);                            \
    ulonglong2 tb1 = *(const ulonglong2 *)(sb + (NN) + 28);                            \
    u64 a0 = ta0.x, a1 = ta0.y, a2 = ta1.x, a3 = ta1.y;                                \
    FMA2(acc0, a0, V0);  FMA2(acc1, a0, V1);  FMA2(acc2, a0, V2);  FMA2(acc3, a0, V3); \
    FMA2(acc4, a0, V4);  FMA2(acc5, a0, V5);  FMA2(acc6, a0, V6);  FMA2(acc7, a0, V7); \
    FMA2(acc0, a1, V1);  FMA2(acc1, a1, V2);  FMA2(acc2, a1, V3);  FMA2(acc3, a1, V4); \
    FMA2(acc4, a1, V5);  FMA2(acc5, a1, V6);  FMA2(acc6, a1, V7);  FMA2(acc7, a1, V8); \
    FMA2(acc0, a2, V2);  FMA2(acc1, a2, V3);  FMA2(acc2, a2, V4);  FMA2(acc3, a2, V5); \
    FMA2(acc4, a2, V6);  FMA2(acc5, a2, V7);  FMA2(acc6, a2, V8);  FMA2(acc7, a2, V9); \
    FMA2(acc0, a3, V3);  FMA2(acc1, a3, V4);  FMA2(acc2, a3, V5);  FMA2(acc3, a3, V6); \
    FMA2(acc4, a3, V7);  FMA2(acc5, a3, V8);  FMA2(acc6, a3, V9);  FMA2(acc7, a3, V10);\
    V12 = tb0.x; V13 = tb0.y; V14 = tb1.x; V15 = tb1.y;                                \
  }

__global__ void __launch_bounds__(64)
acf_kernel(const float* __restrict__ in, float* __restrict__ out)
{
    __shared__ __align__(16) float shm[SHMW];

    const int t   = blockIdx.x;   // frame index 0..299
    const int bf  = blockIdx.y;   // fused (batch, freq) 0..199
    const int tid = threadIdx.x;  // 0..63

    // Exact replica of np.linspace(0, 19488, 300).astype(int64)
    const double delta = (double)(TSAMP - LFRAME) / (double)(NFRAME - 1);
    const int S = (t == NFRAME - 1) ? (TSAMP - LFRAME) : (int)((double)t * delta);

    // -------- load + window + build circular (and shift-by-1) extensions --------
    // input layout: nervegram[b, f, time, c] -> channels adjacent => one float2 per time
    const float2* __restrict__ src = (const float2*)in + (size_t)bf * TSAMP + S;
    #pragma unroll
    for (int it = 0; it < 8; ++it) {
        const int n = tid + 64 * it;                       // 0..511
        const float2 v = src[n];
        const float wn = 0.5f - 0.5f * __cosf((float)n * 0.012271846303085130f); // 2*pi/512
        const float f0 = wn * v.x;
        const float f1 = wn * v.y;
        shm[SW0 + n]        = f0;
        shm[SW0 + EXT + n]  = f1;
        const int m = (n + 511) & 511;                     // n-1 mod 512
        shm[SWS0 + m]       = f0;
        shm[SWS0 + EXT + m] = f1;
        if (n < 292)           { shm[SW0  + n + 512] = f0;  shm[SW0  + EXT + n + 512] = f1; }
        if (n >= 1 && n < 293) { shm[SWS0 + n + 511] = f0;  shm[SWS0 + EXT + n + 511] = f1; }
    }
    __syncthreads();

    // -------- per-thread lag assignment --------
    // warp = channel; lane -> (parity p, group g); lags = 16g + p + {0,2,...,14}
    const int c    = tid >> 5;
    const int lane = tid & 31;
    const int p    = lane & 1;
    const int g    = lane >> 1;
    const int K    = 16 * g + p;

    // Per-thread circular phase rotation r(g) = 4*(g mod 8):
    //  - spreads a-loads over 8 disjoint bank groups (8 distinct words, 1 phase)
    //  - spreads b-loads uniformly over all 8 bank groups (4 words/group, 4 phases)
    // Sum over full circle is rotation-invariant, so results are unchanged.
    const int r = 4 * (g & 7);

    const float* sa = shm + SW0 + EXT * c + r;                              // f_c[(r+tau) mod 512]
    const float* sb = (p ? (shm + SWS0 + EXT * c) : (shm + SW0 + EXT * c))
                      + 16 * g + r;                                          // f_c[(r+tau+K+.) mod 512]

    u64 acc0 = 0, acc1 = 0, acc2 = 0, acc3 = 0, acc4 = 0, acc5 = 0, acc6 = 0, acc7 = 0;
    u64 U0,U1,U2,U3,U4,U5,U6,U7,U8,U9,U10,U11,U12,U13,U14,U15;

    // prologue: U0..U11 = sb[0..23]
    {
        ulonglong2 q;
        q = *(const ulonglong2*)(sb +  0); U0  = q.x; U1  = q.y;
        q = *(const ulonglong2*)(sb +  4); U2  = q.x; U3  = q.y;
        q = *(const ulonglong2*)(sb +  8); U4  = q.x; U5  = q.y;
        q = *(const ulonglong2*)(sb + 12); U6  = q.x; U7  = q.y;
        q = *(const ulonglong2*)(sb + 16); U8  = q.x; U9  = q.y;
        q = *(const ulonglong2*)(sb + 20); U10 = q.x; U11 = q.y;
    }

    // main loop: 64 macro-steps of 8 n-values, window registers rotate with period 4
    for (int n8 = 0; n8 < 512; n8 += 32) {
        STEP(n8,      U0,U1,U2,U3,U4,U5,U6,U7,U8,U9,U10,U11,U12,U13,U14,U15);
        STEP(n8 +  8, U4,U5,U6,U7,U8,U9,U10,U11,U12,U13,U14,U15,U0,U1,U2,U3);
        STEP(n8 + 16, U8,U9,U10,U11,U12,U13,U14,U15,U0,U1,U2,U3,U4,U5,U6,U7);
        STEP(n8 + 24, U12,U13,U14,U15,U0,U1,U2,U3,U4,U5,U6,U7,U8,U9,U10,U11);
    }

    // -------- epilogue: fold packed halves, relu, stage per-channel ACF --------
    float* sacf = shm + ACF0;
    {
        float lo, hi;
        asm("mov.b64 {%0,%1}, %2;" : "=f"(lo), "=f"(hi) : "l"(acc0));
        sacf[c * NLAG + K +  0] = fmaxf(lo + hi, 0.f);
        asm("mov.b64 {%0,%1}, %2;" : "=f"(lo), "=f"(hi) : "l"(acc1));
        sacf[c * NLAG + K +  2] = fmaxf(lo + hi, 0.f);
        asm("mov.b64 {%0,%1}, %2;" : "=f"(lo), "=f"(hi) : "l"(acc2));
        sacf[c * NLAG + K +  4] = fmaxf(lo + hi, 0.f);
        asm("mov.b64 {%0,%1}, %2;" : "=f"(lo), "=f"(hi) : "l"(acc3));
        sacf[c * NLAG + K +  6] = fmaxf(lo + hi, 0.f);
        asm("mov.b64 {%0,%1}, %2;" : "=f"(lo), "=f"(hi) : "l"(acc4));
        sacf[c * NLAG + K +  8] = fmaxf(lo + hi, 0.f);
        asm("mov.b64 {%0,%1}, %2;" : "=f"(lo), "=f"(hi) : "l"(acc5));
        sacf[c * NLAG + K + 10] = fmaxf(lo + hi, 0.f);
        asm("mov.b64 {%0,%1}, %2;" : "=f"(lo), "=f"(hi) : "l"(acc6));
        sacf[c * NLAG + K + 12] = fmaxf(lo + hi, 0.f);
        asm("mov.b64 {%0,%1}, %2;" : "=f"(lo), "=f"(hi) : "l"(acc7));
        sacf[c * NLAG + K + 14] = fmaxf(lo + hi, 0.f);
    }
    __syncthreads();

    // -------- normalize per channel, mean over channels, store --------
    const float n0 = sacf[0];
    const float n1 = sacf[NLAG];
    const float i0 = (n0 == 0.f) ? 1.f : rsqrtf(n0);
    const float i1 = (n1 == 0.f) ? 1.f : rsqrtf(n1);
    float* __restrict__ op = out + ((size_t)bf * NFRAME + t) * NLAG;
    #pragma unroll
    for (int k = tid; k < NLAG; k += 64) {
        op[k] = 0.5f * (sacf[k] * i0 + sacf[NLAG + k] * i1);
    }
}

extern "C" void kernel_launch(void* const* d_in, const int* in_sizes, int n_in,
                              void* d_out, int out_size)
{
    (void)in_sizes; (void)n_in; (void)out_size;
    const float* in = (const float*)d_in[0];
    float* out = (float*)d_out;
    dim3 grid(NFRAME, BFDIM);
    acf_kernel<<<grid, 64>>>(in, out);
}

// round 12
// speedup vs baseline: 6.1457x; 3.1581x over previous
#include <cuda_runtime.h>
#include <math.h>

#define NFRAME 300
#define LFRAME 512
#define NLAG   256
#define TSAMP  20000
#define BFDIM  200          // 4 * 50

// ---- complex helpers (float2) ----
#define CADD(a,b) make_float2((a).x+(b).x, (a).y+(b).y)
#define CSUB(a,b) make_float2((a).x-(b).x, (a).y-(b).y)
#define CMUL(a,b) make_float2(fmaf((a).x,(b).x,-(a).y*(b).y), fmaf((a).x,(b).y,(a).y*(b).x))
#define MULNI(a)  make_float2((a).y, -(a).x)                 // * (-i)
#define SQH 0.70710678118654752f
#define MULW1(a)  make_float2(SQH*((a).x+(a).y), SQH*((a).y-(a).x))   // * e^{-i pi/4}
#define MULW3(a)  make_float2(SQH*((a).y-(a).x), -SQH*((a).x+(a).y))  // * e^{-3i pi/4}

// Twiddle table W512^i = exp(-2*pi*i/512)^i; filled by init kernel each launch
// (graph-capturable: plain kernel node, deterministic).
__device__ float2 g_twid[512];

__global__ void twid_init_kernel() {
    const int i = threadIdx.x;
    const double a = -2.0 * 3.14159265358979323846 * (double)i / 512.0;
    g_twid[i] = make_float2((float)cos(a), (float)sin(a));
}

// In-place 8-point DFT: v[d] <- sum_j v[j] * W8^{j*d}   (verified on impulse inputs)
__device__ __forceinline__ void dft8(float2 v[8]) {
    float2 t0 = CADD(v[0], v[4]), t1 = CSUB(v[0], v[4]);
    float2 t2 = CADD(v[2], v[6]), t3 = CSUB(v[2], v[6]);
    float2 s0 = CADD(v[1], v[5]), s1 = CSUB(v[1], v[5]);
    float2 s2 = CADD(v[3], v[7]), s3 = CSUB(v[3], v[7]);
    float2 E0 = CADD(t0, t2), E2 = CSUB(t0, t2);
    float2 nt3 = MULNI(t3);
    float2 E1 = CADD(t1, nt3), E3 = CSUB(t1, nt3);
    float2 O0 = CADD(s0, s2), O2 = CSUB(s0, s2);
    float2 ns3 = MULNI(s3);
    float2 O1 = CADD(s1, ns3), O3 = CSUB(s1, ns3);
    float2 w1 = MULW1(O1), w2 = MULNI(O2), w3 = MULW3(O3);
    v[0] = CADD(E0, O0); v[4] = CSUB(E0, O0);
    v[1] = CADD(E1, w1); v[5] = CSUB(E1, w1);
    v[2] = CADD(E2, w2); v[6] = CSUB(E2, w2);
    v[3] = CADD(E3, w3); v[7] = CSUB(E3, w3);
}

// Forward 512-pt complex FFT, 64 threads, 8 regs each.
//  n = 64a + 8b + c,  k = d + 8e + 64f  (all radix-8 digits)
//  stage1 (thread tau=8b+c): DFT over a, twiddle W512^{tau*d}
//  stage2 (thread tau=8d+c): DFT over b, twiddle W64^{c*e}
//  stage3 (thread tau=8e+d): DFT over c  ->  regs hold Z[tau + 64f]
// Transposes use layout idx = 72*row + 9*mid + c (stride 72 = 8 mod 16, mid-stride 9:
// transpose LOADS are half-warp bank-bijective -> conflict-free).
__device__ __forceinline__ void fft512(float2* __restrict__ b0, float2* __restrict__ b1,
                                       const float2 tw1[8], const float2 tw2[8],
                                       int tid, float2 v[8], bool store3)
{
    // ---- stage 1: read natural from b0, write L2 layout to b1 ----
    #pragma unroll
    for (int j = 0; j < 8; ++j) v[j] = b0[tid + 64*j];
    dft8(v);
    #pragma unroll
    for (int d = 1; d < 8; ++d) v[d] = CMUL(v[d], tw1[d]);
    {
        const int bq = tid >> 3, c = tid & 7;
        #pragma unroll
        for (int d = 0; d < 8; ++d) b1[72*d + 9*bq + c] = v[d];
    }
    __syncthreads();
    // ---- stage 2: read L2 from b1, write L3 layout to b0 ----
    {
        const int dd = tid >> 3, c = tid & 7;
        #pragma unroll
        for (int j = 0; j < 8; ++j) v[j] = b1[72*dd + 9*j + c];
    }
    dft8(v);
    #pragma unroll
    for (int e = 1; e < 8; ++e) v[e] = CMUL(v[e], tw2[e]);
    {
        const int dd = tid >> 3, c = tid & 7;
        #pragma unroll
        for (int e = 0; e < 8; ++e) b0[72*e + 9*dd + c] = v[e];
    }
    __syncthreads();
    // ---- stage 3: read L3 from b0 -> regs v[f] = Z[tid + 64f]; optionally store natural to b1 ----
    {
        const int ee = tid >> 3, dd = tid & 7;
        #pragma unroll
        for (int j = 0; j < 8; ++j) v[j] = b0[72*ee + 9*dd + j];
    }
    dft8(v);
    if (store3) {
        #pragma unroll
        for (int f = 0; f < 8; ++f) b1[tid + 64*f] = v[f];
    }
}

__global__ void __launch_bounds__(64)
acf_fft_kernel(const float* __restrict__ in, float* __restrict__ out)
{
    __shared__ float2 buf0[576];   // natural z / L3 / Qc-natural / L3
    __shared__ float2 buf1[576];   // L2 / natural spectrum / L2 / Y0

    const int t   = blockIdx.x;   // frame 0..299
    const int bf  = blockIdx.y;   // fused (batch,freq) 0..199
    const int tid = threadIdx.x;  // 0..63

    // Exact replica of np.linspace(0, 19488, 300).astype(int64)
    const double delta = (double)(TSAMP - LFRAME) / (double)(NFRAME - 1);
    const int S = (t == NFRAME - 1) ? (TSAMP - LFRAME) : (int)((double)t * delta);

    // ---- windowed load: z[n] = w[n]*f0[n] + i*w[n]*f1[n]  (channels are the packing!) ----
    const float2* __restrict__ src = (const float2*)in + (size_t)bf * TSAMP + S;
    #pragma unroll
    for (int it = 0; it < 8; ++it) {
        const int n = tid + 64*it;
        const float2 vv = src[n];
        const float wn = 0.5f - 0.5f * __cosf((float)n * 0.012271846303085130f); // 2*pi/512
        buf0[n] = make_float2(wn * vv.x, wn * vv.y);
    }

    // ---- per-thread twiddles (identical roles in both FFTs -> load once) ----
    float2 tw1[8], tw2[8];
    tw1[0] = make_float2(1.f, 0.f);
    tw2[0] = make_float2(1.f, 0.f);
    {
        const int c = tid & 7;
        #pragma unroll
        for (int d = 1; d < 8; ++d) tw1[d] = g_twid[tid * d];      // W512^{tau*d}, max 441
        #pragma unroll
        for (int e = 1; e < 8; ++e) tw2[e] = g_twid[8 * c * e];    // W64^{c*e},   max 392
    }
    __syncthreads();

    float2 v[8];

    // ---- FFT #1: Z = FFT(z); regs v[f] = Z[tid+64f], full spectrum stored in buf1 ----
    fft512(buf0, buf1, tw1, tw2, tid, v, true);
    __syncthreads();

    // ---- spectrum math: Qc[k] = (P0[k] - i*P1[k]) / 512 ----
    // F0 = (Z[k]+conj(Z[N-k]))/2 ; F1 = (Z[k]-conj(Z[N-k]))/(2i)
    #pragma unroll
    for (int j = 0; j < 8; ++j) {
        const int k = tid + 64*j;
        const float2 a = v[j];
        const float2 b = buf1[(512 - k) & 511];
        const float sr = a.x + b.x, di = a.y - b.y;   // Z[k]+conj(Z[m])
        const float dr = a.x - b.x, si = a.y + b.y;   // Z[k]-conj(Z[m])
        const float P0 = sr*sr + di*di;               // 4*|F0|^2
        const float P1 = dr*dr + si*si;               // 4*|F1|^2
        buf0[k] = make_float2(P0 * (0.25f/512.0f), -P1 * (0.25f/512.0f));
    }
    __syncthreads();

    // ---- FFT #2 (forward; linearity gives irfft of both spectra at once) ----
    // Y = FFT(Qc)/1 ;  acf0 = Re Y, acf1 = -Im Y   (both P real-even => Y has the ACFs)
    fft512(buf0, buf1, tw1, tw2, tid, v, false);

    // broadcast Y[0] (held by thread 0) for normalization
    if (tid == 0) buf1[0] = v[0];
    __syncthreads();
    const float2 y0 = buf1[0];
    const float a00 = fmaxf(y0.x, 0.f);
    const float a10 = fmaxf(-y0.y, 0.f);
    const float i0 = (a00 == 0.f) ? 1.f : rsqrtf(a00);
    const float i1 = (a10 == 0.f) ? 1.f : rsqrtf(a10);

    // ---- epilogue: relu, normalize, mean channels, store lags 0..255 ----
    float* __restrict__ op = out + ((size_t)bf * NFRAME + t) * NLAG;
    #pragma unroll
    for (int f = 0; f < 4; ++f) {
        const float aa = fmaxf(v[f].x, 0.f);    // acf0[tid+64f]
        const float bb = fmaxf(-v[f].y, 0.f);   // acf1[tid+64f]
        op[tid + 64*f] = 0.5f * (aa * i0 + bb * i1);
    }
}

extern "C" void kernel_launch(void* const* d_in, const int* in_sizes, int n_in,
                              void* d_out, int out_size)
{
    (void)in_sizes; (void)n_in; (void)out_size;
    const float* in = (const float*)d_in[0];
    float* out = (float*)d_out;
    twid_init_kernel<<<1, 512>>>();
    dim3 grid(NFRAME, BFDIM);
    acf_fft_kernel<<<grid, 64>>>(in, out);
}

// round 14
// speedup vs baseline: 8.8243x; 1.4359x over previous
#include <cuda_runtime.h>
#include <math.h>

#define NFRAME 300
#define LFRAME 512
#define NLAG   256
#define TSAMP  20000
#define BFDIM  200          // 4 * 50

// ---- complex helpers (float2) ----
#define CADD(a,b) make_float2((a).x+(b).x, (a).y+(b).y)
#define CSUB(a,b) make_float2((a).x-(b).x, (a).y-(b).y)
#define CMUL(a,b) make_float2(fmaf((a).x,(b).x,-(a).y*(b).y), fmaf((a).x,(b).y,(a).y*(b).x))
#define MULNI(a)  make_float2((a).y, -(a).x)                 // * (-i)
#define SQH 0.70710678118654752f
#define MULW1(a)  make_float2(SQH*((a).x+(a).y), SQH*((a).y-(a).x))   // * e^{-i pi/4}
#define MULW3(a)  make_float2(SQH*((a).y-(a).x), -SQH*((a).x+(a).y))  // * e^{-3i pi/4}

// Twiddle table W512^i = exp(-2*pi*i/512)^i; filled by init kernel each launch.
__device__ float2 g_twid[512];

__global__ void twid_init_kernel() {
    const int i = threadIdx.x;
    const double a = -2.0 * 3.14159265358979323846 * (double)i / 512.0;
    g_twid[i] = make_float2((float)cos(a), (float)sin(a));
}

// In-place 8-point DFT: v[d] <- sum_j v[j] * W8^{j*d}   (verified on impulse inputs)
__device__ __forceinline__ void dft8(float2 v[8]) {
    float2 t0 = CADD(v[0], v[4]), t1 = CSUB(v[0], v[4]);
    float2 t2 = CADD(v[2], v[6]), t3 = CSUB(v[2], v[6]);
    float2 s0 = CADD(v[1], v[5]), s1 = CSUB(v[1], v[5]);
    float2 s2 = CADD(v[3], v[7]), s3 = CSUB(v[3], v[7]);
    float2 E0 = CADD(t0, t2), E2 = CSUB(t0, t2);
    float2 nt3 = MULNI(t3);
    float2 E1 = CADD(t1, nt3), E3 = CSUB(t1, nt3);
    float2 O0 = CADD(s0, s2), O2 = CSUB(s0, s2);
    float2 ns3 = MULNI(s3);
    float2 O1 = CADD(s1, ns3), O3 = CSUB(s1, ns3);
    float2 w1 = MULW1(O1), w2 = MULNI(O2), w3 = MULW3(O3);
    v[0] = CADD(E0, O0); v[4] = CSUB(E0, O0);
    v[1] = CADD(E1, w1); v[5] = CSUB(E1, w1);
    v[2] = CADD(E2, w2); v[6] = CSUB(E2, w2);
    v[3] = CADD(E3, w3); v[7] = CSUB(E3, w3);
}

// 512-pt FFT tail given stage-1 input ALREADY IN REGISTERS v[j] = x[tid + 64j].
//  n = 64a + 8b + c,  k = d + 8e + 64f
//  stage1: DFT over a (in regs), twiddle W512^{tid*d}, store L2 layout to bA
//  stage2: DFT over b, twiddle W64^{c*e}, store L3 layout to bB
//  stage3: DFT over c -> v[f] = X[tid + 64f]
// Transpose layout idx = 72*row + 9*mid + c: loads are half-warp bank-bijective.
__device__ __forceinline__ void fft512_reg(float2* __restrict__ bA, float2* __restrict__ bB,
                                           const float2 tw1[8], const float2 tw2[8],
                                           int tid, float2 v[8])
{
    const int hi = tid >> 3, lo = tid & 7;
    // ---- stage 1 (input in regs) ----
    dft8(v);
    #pragma unroll
    for (int d = 1; d < 8; ++d) v[d] = CMUL(v[d], tw1[d]);
    #pragma unroll
    for (int d = 0; d < 8; ++d) bA[72*d + 9*hi + lo] = v[d];
    __syncthreads();
    // ---- stage 2 ----
    #pragma unroll
    for (int j = 0; j < 8; ++j) v[j] = bA[72*hi + 9*j + lo];
    dft8(v);
    #pragma unroll
    for (int e = 1; e < 8; ++e) v[e] = CMUL(v[e], tw2[e]);
    #pragma unroll
    for (int e = 0; e < 8; ++e) bB[72*e + 9*hi + lo] = v[e];
    __syncthreads();
    // ---- stage 3 ----
    #pragma unroll
    for (int j = 0; j < 8; ++j) v[j] = bB[72*hi + 9*lo + j];
    dft8(v);   // v[f] = X[tid + 64f]
}

__global__ void __launch_bounds__(64)
acf_fft_kernel(const float* __restrict__ in, float* __restrict__ out)
{
    __shared__ float2 buf0[576];
    __shared__ float2 buf1[576];

    const int t   = blockIdx.x;   // frame 0..299
    const int bf  = blockIdx.y;   // fused (batch,freq) 0..199
    const int tid = threadIdx.x;  // 0..63

    // Exact replica of np.linspace(0, 19488, 300).astype(int64)
    const double delta = (double)(TSAMP - LFRAME) / (double)(NFRAME - 1);
    const int S = (t == NFRAME - 1) ? (TSAMP - LFRAME) : (int)((double)t * delta);

    // ---- windowed load DIRECTLY into registers: v[j] = z[tid+64j] = w*f0 + i*w*f1 ----
    float2 v[8];
    const float2* __restrict__ src = (const float2*)in + (size_t)bf * TSAMP + S;
    #pragma unroll
    for (int j = 0; j < 8; ++j) {
        const int n = tid + 64*j;
        const float2 vv = src[n];
        const float wn = 0.5f - 0.5f * __cosf((float)n * 0.012271846303085130f); // 2*pi/512
        v[j] = make_float2(wn * vv.x, wn * vv.y);
    }

    // ---- twiddles via power chains: 2 LDG instead of 14 ----
    float2 tw1[8], tw2[8];
    tw1[0] = make_float2(1.f, 0.f);
    tw2[0] = make_float2(1.f, 0.f);
    {
        const float2 w = g_twid[tid];            // W512^tid
        const float2 u = g_twid[8 * (tid & 7)];  // W64^c
        tw1[1] = w;
        tw2[1] = u;
        #pragma unroll
        for (int d = 2; d < 8; ++d) tw1[d] = CMUL(tw1[d-1], w);
        #pragma unroll
        for (int e = 2; e < 8; ++e) tw2[e] = CMUL(tw2[e-1], u);
    }

    // ---- FFT #1: L2->buf1, L3->buf0; v[f] = Z[tid+64f] ----
    fft512_reg(buf1, buf0, tw1, tw2, tid, v);

    // store natural-order Z for the reversed-index pairing
    #pragma unroll
    for (int f = 0; f < 8; ++f) buf1[tid + 64*f] = v[f];
    __syncthreads();

    // ---- spectrum math IN REGISTERS: Qc[k] = (P0[k] - i*P1[k]) / 512 ----
    // F0 = (Z[k]+conj(Z[N-k]))/2 ; F1 = (Z[k]-conj(Z[N-k]))/(2i)
    #pragma unroll
    for (int j = 0; j < 8; ++j) {
        const int k = tid + 64*j;
        const float2 a = v[j];
        const float2 b = buf1[(512 - k) & 511];
        const float sr = a.x + b.x, di = a.y - b.y;   // Z[k]+conj(Z[m])
        const float dr = a.x - b.x, si = a.y + b.y;   // Z[k]-conj(Z[m])
        const float P0 = sr*sr + di*di;               // 4*|F0|^2
        const float P1 = dr*dr + si*si;               // 4*|F1|^2
        v[j] = make_float2(P0 * (0.25f/512.0f), -P1 * (0.25f/512.0f));
    }

    // ---- FFT #2 on Qc (already in regs): L2->buf0 (free), L3->buf1 ----
    // buf0 stage-3 reads of FFT1 completed before the Z-store sync; spectrum's
    // buf1 reads complete before fft's internal sync that precedes buf1 stores.
    fft512_reg(buf0, buf1, tw1, tw2, tid, v);
    // v[f] = Y[tid+64f];  acf0 = Re Y, acf1 = -Im Y

    // ---- broadcast Y[0] (thread 0) for normalization ----
    if (tid == 0) buf0[0] = v[0];
    __syncthreads();
    const float2 y0 = buf0[0];
    const float a00 = fmaxf(y0.x, 0.f);
    const float a10 = fmaxf(-y0.y, 0.f);
    const float i0 = (a00 == 0.f) ? 1.f : rsqrtf(a00);
    const float i1 = (a10 == 0.f) ? 1.f : rsqrtf(a10);

    // ---- epilogue: relu, normalize, mean channels, store lags 0..255 ----
    float* __restrict__ op = out + ((size_t)bf * NFRAME + t) * NLAG;
    #pragma unroll
    for (int f = 0; f < 4; ++f) {
        const float aa = fmaxf(v[f].x, 0.f);    // acf0[tid+64f]
        const float bb = fmaxf(-v[f].y, 0.f);   // acf1[tid+64f]
        op[tid + 64*f] = 0.5f * (aa * i0 + bb * i1);
    }
}

extern "C" void kernel_launch(void* const* d_in, const int* in_sizes, int n_in,
                              void* d_out, int out_size)
{
    (void)in_sizes; (void)n_in; (void)out_size;
    const float* in = (const float*)d_in[0];
    float* out = (float*)d_out;
    twid_init_kernel<<<1, 512>>>();
    dim3 grid(NFRAME, BFDIM);
    acf_fft_kernel<<<grid, 64>>>(in, out);
}

// round 16
// speedup vs baseline: 9.7930x; 1.1098x over previous
#include <cuda_runtime.h>
#include <math.h>

#define NFRAME 300
#define LFRAME 512
#define NLAG   256
#define TSAMP  20000
#define BFDIM  200          // 4 * 50

// ---- complex helpers (float2) ----
#define CADD(a,b) make_float2((a).x+(b).x, (a).y+(b).y)
#define CSUB(a,b) make_float2((a).x-(b).x, (a).y-(b).y)
#define CMUL(a,b) make_float2(fmaf((a).x,(b).x,-(a).y*(b).y), fmaf((a).x,(b).y,(a).y*(b).x))
#define MULNI(a)  make_float2((a).y, -(a).x)                 // * (-i)
#define SQH 0.70710678118654752f
#define MULW1(a)  make_float2(SQH*((a).x+(a).y), SQH*((a).y-(a).x))   // * e^{-i pi/4}
#define MULW3(a)  make_float2(SQH*((a).y-(a).x), -SQH*((a).x+(a).y))  // * e^{-3i pi/4}

// Twiddle table W512^i = exp(-2*pi*i/512)^i; filled by init kernel each launch.
__device__ float2 g_twid[512];

__global__ void twid_init_kernel() {
    const int i = threadIdx.x;
    const double a = -2.0 * 3.14159265358979323846 * (double)i / 512.0;
    g_twid[i] = make_float2((float)cos(a), (float)sin(a));
}

// In-place 8-point DFT: v[d] <- sum_j v[j] * W8^{j*d}   (verified on impulse inputs)
__device__ __forceinline__ void dft8(float2 v[8]) {
    float2 t0 = CADD(v[0], v[4]), t1 = CSUB(v[0], v[4]);
    float2 t2 = CADD(v[2], v[6]), t3 = CSUB(v[2], v[6]);
    float2 s0 = CADD(v[1], v[5]), s1 = CSUB(v[1], v[5]);
    float2 s2 = CADD(v[3], v[7]), s3 = CSUB(v[3], v[7]);
    float2 E0 = CADD(t0, t2), E2 = CSUB(t0, t2);
    float2 nt3 = MULNI(t3);
    float2 E1 = CADD(t1, nt3), E3 = CSUB(t1, nt3);
    float2 O0 = CADD(s0, s2), O2 = CSUB(s0, s2);
    float2 ns3 = MULNI(s3);
    float2 O1 = CADD(s1, ns3), O3 = CSUB(s1, ns3);
    float2 w1 = MULW1(O1), w2 = MULNI(O2), w3 = MULW3(O3);
    v[0] = CADD(E0, O0); v[4] = CSUB(E0, O0);
    v[1] = CADD(E1, w1); v[5] = CSUB(E1, w1);
    v[2] = CADD(E2, w2); v[6] = CSUB(E2, w2);
    v[3] = CADD(E3, w3); v[7] = CSUB(E3, w3);
}

// 512-pt FFT, stage-1 input ALREADY IN REGISTERS v[j] = x[tid + 64j].
//  n = 64a + 8b + c,  k = d + 8e + 64f
//  stage1: DFT over a, twiddle W512^{tid*d}, store to bA at [72d + 8b + c]
//          (mid-stride 8: store half-warp set {0..15} -> conflict-free;
//           stage-2 load set {72hi+lo} -> banks {2lo}u{16+2lo} -> conflict-free)
//  stage2: DFT over b, twiddle W64^{c*e}, store to bB at [72e + 9d + c]
//          (stride 9: stage-3 loads bank-bijective; stores have one 2-way pair)
//  stage3: DFT over c -> v[f] = X[tid + 64f]
__device__ __forceinline__ void fft512_reg(float2* __restrict__ bA, float2* __restrict__ bB,
                                           const float2 tw1[8], const float2 tw2[8],
                                           int tid, float2 v[8])
{
    const int hi = tid >> 3, lo = tid & 7;
    // ---- stage 1 (input in regs) ----
    dft8(v);
    #pragma unroll
    for (int d = 1; d < 8; ++d) v[d] = CMUL(v[d], tw1[d]);
    #pragma unroll
    for (int d = 0; d < 8; ++d) bA[72*d + 8*hi + lo] = v[d];
    __syncthreads();
    // ---- stage 2 ----
    #pragma unroll
    for (int j = 0; j < 8; ++j) v[j] = bA[72*hi + 8*j + lo];
    dft8(v);
    #pragma unroll
    for (int e = 1; e < 8; ++e) v[e] = CMUL(v[e], tw2[e]);
    #pragma unroll
    for (int e = 0; e < 8; ++e) bB[72*e + 9*hi + lo] = v[e];
    __syncthreads();
    // ---- stage 3 ----
    #pragma unroll
    for (int j = 0; j < 8; ++j) v[j] = bB[72*hi + 9*lo + j];
    dft8(v);   // v[f] = X[tid + 64f]
}

__global__ void __launch_bounds__(64)
acf_fft_kernel(const float* __restrict__ in, float* __restrict__ out)
{
    __shared__ float2 buf0[576];
    __shared__ float2 buf1[576];

    const int t   = blockIdx.x;   // frame 0..299
    const int bf  = blockIdx.y;   // fused (batch,freq) 0..199
    const int tid = threadIdx.x;  // 0..63

    // Exact replica of np.linspace(0, 19488, 300).astype(int64)
    const double delta = (double)(TSAMP - LFRAME) / (double)(NFRAME - 1);
    const int S = (t == NFRAME - 1) ? (TSAMP - LFRAME) : (int)((double)t * delta);

    // ---- windowed load DIRECTLY into registers: v[j] = z[tid+64j] = w*f0 + i*w*f1 ----
    float2 v[8];
    const float2* __restrict__ src = (const float2*)in + (size_t)bf * TSAMP + S;
    #pragma unroll
    for (int j = 0; j < 8; ++j) {
        const int n = tid + 64*j;
        const float2 vv = src[n];
        const float wn = 0.5f - 0.5f * __cosf((float)n * 0.012271846303085130f); // 2*pi/512
        v[j] = make_float2(wn * vv.x, wn * vv.y);
    }

    // ---- twiddles via power chains: 2 LDG instead of 14 ----
    float2 tw1[8], tw2[8];
    tw1[0] = make_float2(1.f, 0.f);
    tw2[0] = make_float2(1.f, 0.f);
    {
        const float2 w = g_twid[tid];            // W512^tid
        const float2 u = g_twid[8 * (tid & 7)];  // W64^c
        tw1[1] = w;
        tw2[1] = u;
        #pragma unroll
        for (int d = 2; d < 8; ++d) tw1[d] = CMUL(tw1[d-1], w);
        #pragma unroll
        for (int e = 2; e < 8; ++e) tw2[e] = CMUL(tw2[e-1], u);
    }

    // ---- FFT #1: A=buf1, B=buf0; v[f] = Z[tid+64f] ----
    fft512_reg(buf1, buf0, tw1, tw2, tid, v);

    // ---- store Z in exchange layout: Z[64f + t] at [9t + f]  (max idx 574 < 576)
    // Store lanes (fixed f, t varies): banks 18t mod 32 -> bijective per half-warp.
    // buf1 is dead after FFT1's stage-2 loads, so no extra sync needed before store.
    #pragma unroll
    for (int f = 0; f < 8; ++f) buf1[9*tid + f] = v[f];
    __syncthreads();

    // ---- spectrum math IN REGISTERS: Qc[k] = (P0[k] - i*P1[k]) / 512 ----
    // F0 = (Z[k]+conj(Z[N-k]))/2 ; F1 = (Z[k]-conj(Z[N-k]))/(2i)
    #pragma unroll
    for (int j = 0; j < 8; ++j) {
        const int k2 = (512 - tid - 64*j) & 511;          // N-k
        const float2 a = v[j];
        const float2 b = buf1[9*(k2 & 63) + (k2 >> 6)];   // Z[N-k] via exchange layout
        const float sr = a.x + b.x, di = a.y - b.y;       // Z[k]+conj(Z[m])
        const float dr = a.x - b.x, si = a.y + b.y;       // Z[k]-conj(Z[m])
        const float P0 = sr*sr + di*di;                   // 4*|F0|^2
        const float P1 = dr*dr + si*si;                   // 4*|F1|^2
        v[j] = make_float2(P0 * (0.25f/512.0f), -P1 * (0.25f/512.0f));
    }

    // ---- FFT #2 on Qc (in regs): A=buf0, B=buf1 ----
    // buf0 stage-3 reads of FFT1 are pre-spectrum-sync; spectrum's buf1 reads
    // complete before FFT2's internal sync that precedes its buf1 stores.
    fft512_reg(buf0, buf1, tw1, tw2, tid, v);
    // v[f] = Y[tid+64f];  acf0 = Re Y, acf1 = -Im Y

    // ---- broadcast Y[0] (thread 0) for normalization ----
    if (tid == 0) buf0[0] = v[0];
    __syncthreads();
    const float2 y0 = buf0[0];
    const float a00 = fmaxf(y0.x, 0.f);
    const float a10 = fmaxf(-y0.y, 0.f);
    const float i0 = (a00 == 0.f) ? 1.f : rsqrtf(a00);
    const float i1 = (a10 == 0.f) ? 1.f : rsqrtf(a10);

    // ---- epilogue: relu, normalize, mean channels, store lags 0..255 ----
    float* __restrict__ op = out + ((size_t)bf * NFRAME + t) * NLAG;
    #pragma unroll
    for (int f = 0; f < 4; ++f) {
        const float aa = fmaxf(v[f].x, 0.f);    // acf0[tid+64f]
        const float bb = fmaxf(-v[f].y, 0.f);   // acf1[tid+64f]
        op[tid + 64*f] = 0.5f * (aa * i0 + bb * i1);
    }
}

extern "C" void kernel_launch(void* const* d_in, const int* in_sizes, int n_in,
                              void* d_out, int out_size)
{
    (void)in_sizes; (void)n_in; (void)out_size;
    const float* in = (const float*)d_in[0];
    float* out = (float*)d_out;
    twid_init_kernel<<<1, 512>>>();
    dim3 grid(NFRAME, BFDIM);
    acf_fft_kernel<<<grid, 64>>>(in, out);
}

// round 17
// speedup vs baseline: 10.6927x; 1.0919x over previous
#include <cuda_runtime.h>
#include <math.h>

#define NFRAME 300
#define LFRAME 512
#define NLAG   256
#define TSAMP  20000
#define BFDIM  200          // 4 * 50

// ---- complex helpers (float2) ----
#define CADD(a,b) make_float2((a).x+(b).x, (a).y+(b).y)
#define CSUB(a,b) make_float2((a).x-(b).x, (a).y-(b).y)
#define CMUL(a,b) make_float2(fmaf((a).x,(b).x,-(a).y*(b).y), fmaf((a).x,(b).y,(a).y*(b).x))
#define MULNI(a)  make_float2((a).y, -(a).x)                 // * (-i)
#define SQH 0.70710678118654752f
#define MULW1(a)  make_float2(SQH*((a).x+(a).y), SQH*((a).y-(a).x))   // * e^{-i pi/4}
#define MULW3(a)  make_float2(SQH*((a).y-(a).x), -SQH*((a).x+(a).y))  // * e^{-3i pi/4}

// In-place 8-point DFT: v[d] <- sum_j v[j] * W8^{j*d}   (verified on impulse inputs)
__device__ __forceinline__ void dft8(float2 v[8]) {
    float2 t0 = CADD(v[0], v[4]), t1 = CSUB(v[0], v[4]);
    float2 t2 = CADD(v[2], v[6]), t3 = CSUB(v[2], v[6]);
    float2 s0 = CADD(v[1], v[5]), s1 = CSUB(v[1], v[5]);
    float2 s2 = CADD(v[3], v[7]), s3 = CSUB(v[3], v[7]);
    float2 E0 = CADD(t0, t2), E2 = CSUB(t0, t2);
    float2 nt3 = MULNI(t3);
    float2 E1 = CADD(t1, nt3), E3 = CSUB(t1, nt3);
    float2 O0 = CADD(s0, s2), O2 = CSUB(s0, s2);
    float2 ns3 = MULNI(s3);
    float2 O1 = CADD(s1, ns3), O3 = CSUB(s1, ns3);
    float2 w1 = MULW1(O1), w2 = MULNI(O2), w3 = MULW3(O3);
    v[0] = CADD(E0, O0); v[4] = CSUB(E0, O0);
    v[1] = CADD(E1, w1); v[5] = CSUB(E1, w1);
    v[2] = CADD(E2, w2); v[6] = CSUB(E2, w2);
    v[3] = CADD(E3, w3); v[7] = CSUB(E3, w3);
}

__global__ void __launch_bounds__(64)
acf_fft_kernel(const float* __restrict__ in, float* __restrict__ out)
{
    __shared__ float2 buf0[576];
    __shared__ float2 buf1[576];

    const int t   = blockIdx.x;   // frame 0..299
    const int bf  = blockIdx.y;   // fused (batch,freq) 0..199
    const int tid = threadIdx.x;  // 0..63

    // Exact replica of np.linspace(0, 19488, 300).astype(int64)
    const double delta = (double)(TSAMP - LFRAME) / (double)(NFRAME - 1);
    const int S = (t == NFRAME - 1) ? (TSAMP - LFRAME) : (int)((double)t * delta);

    // ---- windowed load DIRECTLY into registers: v[j] = z[tid+64j] = w*f0 + i*w*f1 ----
    float2 v[8];
    const float2* __restrict__ src = (const float2*)in + (size_t)bf * TSAMP + S;
    #pragma unroll
    for (int j = 0; j < 8; ++j) {
        const int n = tid + 64*j;
        const float2 vv = src[n];
        const float wn = 0.5f - 0.5f * __cosf((float)n * 0.012271846303085130f); // 2*pi/512
        v[j] = make_float2(wn * vv.x, wn * vv.y);
    }

    // ---- twiddle seeds in-kernel (sincospif, <=2ulp; args < 0.25*pi) ----
    // w = W512^tid = exp(-i*pi*tid/256), u = W64^c = exp(-i*pi*c/32)
    float2 tw1[8], tw2[8];
    tw1[0] = make_float2(1.f, 0.f);
    tw2[0] = make_float2(1.f, 0.f);
    {
        float2 w, u;
        sincospif(-(float)tid * (1.0f/256.0f), &w.y, &w.x);
        sincospif(-(float)(tid & 7) * (1.0f/32.0f), &u.y, &u.x);
        tw1[1] = w;
        tw2[1] = u;
        #pragma unroll
        for (int d = 2; d < 8; ++d) tw1[d] = CMUL(tw1[d-1], w);
        #pragma unroll
        for (int e = 2; e < 8; ++e) tw2[e] = CMUL(tw2[e-1], u);
    }

    const int hi = tid >> 3, lo = tid & 7;

    // ================= FFT #1 =================
    // stage 1: DFT over a (regs), twiddle W512^{tid*d}, store [72d + 8hi + lo]
    dft8(v);
    #pragma unroll
    for (int d = 1; d < 8; ++d) v[d] = CMUL(v[d], tw1[d]);
    #pragma unroll
    for (int d = 0; d < 8; ++d) buf1[72*d + 8*hi + lo] = v[d];
    __syncthreads();
    // stage 2: load [72hi + 8j + lo], DFT over b, twiddle W64^{c*e}, store [72e + 9hi + lo]
    #pragma unroll
    for (int j = 0; j < 8; ++j) v[j] = buf1[72*hi + 8*j + lo];
    dft8(v);
    #pragma unroll
    for (int e = 1; e < 8; ++e) v[e] = CMUL(v[e], tw2[e]);
    #pragma unroll
    for (int e = 0; e < 8; ++e) buf0[72*e + 9*hi + lo] = v[e];
    __syncthreads();
    // stage 3: load OWN group -> Z[tid+64f], and MIRROR group -> Z[(64-tid)+64f]
    // (mirror load lanes: addr spacing 9 -> banks step -18 mod 32 -> bijective)
    float2 vm[8];
    {
        const int m = (64 - tid) & 63;
        const int mhi = m >> 3, mlo = m & 7;
        #pragma unroll
        for (int j = 0; j < 8; ++j) {
            v[j]  = buf0[72*hi  + 9*lo  + j];
            vm[j] = buf0[72*mhi + 9*mlo + j];
        }
    }
    dft8(v);    // v[f]  = Z[tid + 64f]
    dft8(vm);   // vm[f] = Z[((64-tid)&63) + 64f]

    // tid==0 wraparound: need b = vm[(8-f)&7] instead of vm[7-f]; rotate vm once
    // (uniform predicated moves, constant indices -> stays in registers)
    if (tid == 0) {
        float2 r0 = vm[0];
        vm[0] = vm[1]; vm[1] = vm[2]; vm[2] = vm[3]; vm[3] = vm[4];
        vm[4] = vm[5]; vm[5] = vm[6]; vm[6] = vm[7]; vm[7] = r0;
    }

    // ---- spectrum IN REGISTERS: Qc[k] = (P0[k] - i*P1[k]) / 512 ----
    // a = Z[k], b = Z[N-k] = vm[7-f]
    #pragma unroll
    for (int f = 0; f < 8; ++f) {
        const float2 a = v[f];
        const float2 b = vm[7 - f];
        const float sr = a.x + b.x, di = a.y - b.y;   // Z[k]+conj(Z[N-k])
        const float dr = a.x - b.x, si = a.y + b.y;   // Z[k]-conj(Z[N-k])
        const float P0 = sr*sr + di*di;               // 4*|F0|^2
        const float P1 = dr*dr + si*si;               // 4*|F1|^2
        v[f] = make_float2(P0 * (0.25f/512.0f), -P1 * (0.25f/512.0f));
    }

    // ================= FFT #2 (input already in regs) =================
    // stage 1 -> buf1 (dead since FFT1-s2 + sync; buf0 still being read elsewhere is fine)
    dft8(v);
    #pragma unroll
    for (int d = 1; d < 8; ++d) v[d] = CMUL(v[d], tw1[d]);
    #pragma unroll
    for (int d = 0; d < 8; ++d) buf1[72*d + 8*hi + lo] = v[d];
    __syncthreads();
    // stage 2 -> buf0 (all FFT1-s3 reads ordered before the sync above)
    #pragma unroll
    for (int j = 0; j < 8; ++j) v[j] = buf1[72*hi + 8*j + lo];
    dft8(v);
    #pragma unroll
    for (int e = 1; e < 8; ++e) v[e] = CMUL(v[e], tw2[e]);
    #pragma unroll
    for (int e = 0; e < 8; ++e) buf0[72*e + 9*hi + lo] = v[e];
    __syncthreads();
    // stage 3
    #pragma unroll
    for (int j = 0; j < 8; ++j) v[j] = buf0[72*hi + 9*lo + j];
    dft8(v);    // v[f] = Y[tid + 64f];  acf0 = Re Y, acf1 = -Im Y

    // ---- broadcast Y[0] (thread 0) for normalization ----
    if (tid == 0) buf0[0] = v[0];   // own slot: only thread 0 read buf0[0] at s3
    __syncthreads();
    const float2 y0 = buf0[0];
    const float a00 = fmaxf(y0.x, 0.f);
    const float a10 = fmaxf(-y0.y, 0.f);
    const float i0 = (a00 == 0.f) ? 1.f : rsqrtf(a00);
    const float i1 = (a10 == 0.f) ? 1.f : rsqrtf(a10);

    // ---- epilogue: relu, normalize, mean channels, store lags 0..255 ----
    float* __restrict__ op = out + ((size_t)bf * NFRAME + t) * NLAG;
    #pragma unroll
    for (int f = 0; f < 4; ++f) {
        const float aa = fmaxf(v[f].x, 0.f);    // acf0[tid+64f]
        const float bb = fmaxf(-v[f].y, 0.f);   // acf1[tid+64f]
        op[tid + 64*f] = 0.5f * (aa * i0 + bb * i1);
    }
}

extern "C" void kernel_launch(void* const* d_in, const int* in_sizes, int n_in,
                              void* d_out, int out_size)
{
    (void)in_sizes; (void)n_in; (void)out_size;
    const float* in = (const float*)d_in[0];
    float* out = (float*)d_out;
    dim3 grid(NFRAME, BFDIM);
    acf_fft_kernel<<<grid, 64>>>(in, out);
}